// round 12
// baseline (speedup 1.0000x reference)
#include <cuda_runtime.h>

// Janossy pooling, k=2, n=2048, d=32 — ONE kernel, tiled pair-sum.
// Grid 64 (16 itiles x 4 j-slices, JT=512): halves REDG depth per out-address
// and CTA count at constant per-block row work.
//
// out[1][d] = (1/C) sum_i r_i x_i[d],  out[0][d] = (1/C) sum_i (n-1-r_i) x_i[d]
// Keys pairwise distinct (iid normals) -> strict '<' counting gives exact
// stable rank (validated since R9). Block (itile,jslice): 128 i-rows x 512
// j-keys; partial count c per row; complement handled algebraically:
// acc0 = (512 - [rows in slice])*Σx - acc1, rows-in-slice iff itile>>2==jslice.
//
// Replay-safe zeroing: block 0 / warp 1 atomicExch-zeroes out[0:64] (after its
// loads issue), fences, bumps monotone g_zflag. Warp 0 of each block takes a
// monotone ticket (epoch = tick/GRID) and acquire-polls g_zflag >= epoch+1
// BEFORE compute; program order puts the final RED.ADDs after the acquire.

#define NROWS 2048
#define NDIM  32
#define BLOCK 256                 // 8 warps x 16 rows = 128 rows per block
#define JT    512                 // keys per j-slice
#define GRID  64                  // 16 itiles x 4 jslices

__device__ unsigned int g_start;  // monotone entry ticket
__device__ unsigned int g_zflag;  // monotone "out zeroed" epoch counter

__global__ __launch_bounds__(BLOCK) void janossy_g64(const float* __restrict__ X,
                                                     float* __restrict__ out) {
    __shared__ float skeys[JT];
    __shared__ float sacc[2 * NDIM];

    const int tid    = threadIdx.x;
    const int warp   = tid >> 5;
    const int lane   = tid & 31;
    const int itile  = blockIdx.x >> 2;    // 0..15
    const int jslice = blockIdx.x & 3;     // 0..3

    // ---- 1) Issue ALL global loads first (fly while protocol runs).
    const float kj0 = X[(jslice * JT + tid) * NDIM];         // strided keys
    const float kj1 = X[(jslice * JT + tid + 256) * NDIM];

    const int rbase = itile * 128 + warp * 16;
    float xr[16];
    #pragma unroll
    for (int t = 0; t < 16; t++) xr[t] = X[(rbase + t) * NDIM + lane];

    // ---- 2) Protocol work overlapped with loads in flight.
    if (blockIdx.x == 0 && warp == 1) {
        atomicExch(&out[lane], 0.0f);
        atomicExch(&out[lane + NDIM], 0.0f);
        __syncwarp();
        __threadfence();                   // release zeros before flag
        if (lane == 0) atomicAdd(&g_zflag, 1u);
    }
    if (warp == 0) {
        unsigned target;
        if (lane == 0) target = atomicAdd(&g_start, 1u) / GRID + 1u;
        target = __shfl_sync(0xffffffffu, target, 0);
        unsigned v;
        do {
            asm volatile("ld.acquire.gpu.u32 %0, [%1];" : "=r"(v) : "l"(&g_zflag));
        } while (v < target);
    }

    // ---- 3) Stage keys, init sacc, sync.
    skeys[tid]       = kj0;
    skeys[tid + 256] = kj1;
    if (tid < 2 * NDIM) sacc[tid] = 0.0f;
    __syncthreads();

    // ---- 4) Compute: strict-< partial rank counts (2 instr/elem, free).
    const float4* sk4 = reinterpret_cast<const float4*>(skeys);
    float acc1 = 0.0f, sx = 0.0f;          // lane == feature dim

    #pragma unroll
    for (int t = 0; t < 16; t++) {
        const float x  = xr[t];
        const float xi = __shfl_sync(0xffffffffu, x, 0);   // key_i = x_i[0]

        int cnt = 0;
        #pragma unroll
        for (int m = 0; m < 4; m++) {                      // 128 float4 = 512 keys
            const float4 kv = sk4[lane + m * 32];          // LDS.128, conflict-free
            cnt += (int)(kv.x < xi);
            cnt += (int)(kv.y < xi);
            cnt += (int)(kv.z < xi);
            cnt += (int)(kv.w < xi);
        }
        const int c = __reduce_add_sync(0xffffffffu, cnt); // partial rank
        acc1 += (float)c * x;
        sx   += x;
    }

    // Complement: this block's rows lie in its key slice iff itile>>2 == jslice.
    const float diag = (float)(JT - (int)((itile >> 2) == jslice));
    const float acc0 = diag * sx - acc1;

    const float invC = 1.0f / 2096128.0f;
    atomicAdd(&sacc[lane],        acc0 * invC);
    atomicAdd(&sacc[NDIM + lane], acc1 * invC);
    __syncthreads();

    // ---- 5) Epilogue: fire-and-forget RED.ADD (depth 64 per address now).
    if (warp == 0) {
        atomicAdd(&out[lane],        sacc[lane]);
        atomicAdd(&out[lane + NDIM], sacc[lane + NDIM]);
    }
}

extern "C" void kernel_launch(void* const* d_in, const int* in_sizes, int n_in,
                              void* d_out, int out_size) {
    const float* X = (const float*)d_in[0];
    janossy_g64<<<GRID, BLOCK>>>(X, (float*)d_out);
}